// round 15
// baseline (speedup 1.0000x reference)
#include <cuda_runtime.h>
#include <math.h>
#include <stdint.h>

// ---------------- problem constants ----------------
#define BB    8192
#define DIN   784
#define HID   512
#define LDIM  16
#define CDIM  32
#define OHID  256
#define WIDN  256
#define P3SZ  (3*WIDN*LDIM + WIDN)   // 12544
#define NTT   33

#define OFF_XP   (BB*DIN)
#define OFF_MEAN (OFF_XP + 1)
#define OFF_STD  (OFF_MEAN + BB*LDIM)

typedef unsigned long long ull;

// ---------------- f32x2 helpers ----------------
__device__ __forceinline__ ull f2dup(float x) {
    ull r; asm("mov.b64 %0, {%1, %1};" : "=l"(r) : "f"(x)); return r;
}
__device__ __forceinline__ ull f2pack(float x, float y) {
    ull r; asm("mov.b64 %0, {%1, %2};" : "=l"(r) : "f"(x), "f"(y)); return r;
}
__device__ __forceinline__ void f2unpack(ull v, float& x, float& y) {
    asm("mov.b64 {%0, %1}, %2;" : "=f"(x), "=f"(y) : "l"(v));
}
__device__ __forceinline__ void ffma2(ull& d, ull a, ull b) {
    asm("fma.rn.f32x2 %0, %1, %2, %0;" : "+l"(d) : "l"(a), "l"(b));
}

// ---------------- fast transcendentals (CNF only) ----------------
__device__ __forceinline__ float tanha(float x) {
    float r; asm("tanh.approx.f32 %0, %1;" : "=f"(r) : "f"(x)); return r;
}
__device__ __forceinline__ float sigma_fast(float x) {
    float t = -1.4426950408889634f * x;
    float e; asm("ex2.approx.f32 %0, %1;" : "=f"(e) : "f"(t));
    float d = 1.0f + e;
    float r; asm("rcp.approx.f32 %0, %1;" : "=f"(r) : "f"(d));
    return r;
}

__device__ __forceinline__ float sigm(float x) { return 1.0f/(1.0f+expf(-x)); }

// ---------------- tf32 helpers ----------------
__device__ __forceinline__ void tf32_split(float v, float& hi, float& lo) {
    uint32_t h; asm("cvt.rna.tf32.f32 %0, %1;" : "=r"(h) : "f"(v));
    float hf = __uint_as_float(h);
    float lf = v - hf;
    uint32_t l; asm("cvt.rna.tf32.f32 %0, %1;" : "=r"(l) : "f"(lf));
    hi = hf; lo = __uint_as_float(l);
}
__device__ __forceinline__ void mma_tf32(float* c, const uint32_t* a, const uint32_t* b) {
    asm("mma.sync.aligned.m16n8k8.row.col.f32.tf32.tf32.f32 "
        "{%0,%1,%2,%3}, {%4,%5,%6,%7}, {%8,%9}, {%0,%1,%2,%3};"
        : "+f"(c[0]), "+f"(c[1]), "+f"(c[2]), "+f"(c[3])
        : "r"(a[0]), "r"(a[1]), "r"(a[2]), "r"(a[3]), "r"(b[0]), "r"(b[1]));
}

// ---------------- device scratch ----------------
__device__ float  g_bufA[BB*HID];
__device__ float  g_bufB[BB*HID];
__device__ float  g_ms[BB*2*LDIM];
__device__ float  g_z[BB*LDIM];
__device__ float  g_bc[BB*CDIM];
__device__ float  g_x2[NTT*OHID];
__device__ float  g_p[NTT*P3SZ];
__device__ float4 g_Wp[NTT*16*64];
__device__ float4 g_Up[NTT*16*64];
__device__ float4 g_Bp[NTT*64];
__device__ float4 g_wup[NTT*64];

// ---------------- IN-BLOCK HYBRID GEMM ----------------
// 128x128 tile per block, 256 threads.
// warps 0-3 (one/SMSP): fp32 SIMT (FFMA2 pipe) on rows 64..127
// warps 4-7 (one/SMSP): tf32x3 HMMA (tensor pipe) on rows 0..63
// tf32 hi/lo splits are produced ONCE at staging (cheap), so the tensor
// warps issue almost no fma-pipe work in the mainloop.
enum { ACT_NONE=0, ACT_ELU=1, ACT_TANH=2, ACT_SIG=3 };

template<int ACT> __device__ __forceinline__ float actf(float v) {
    if (ACT == ACT_ELU)  return (v > 0.0f) ? v : expm1f(v);
    if (ACT == ACT_TANH) return tanhf(v);
    if (ACT == ACT_SIG)  return 1.0f/(1.0f+expf(-v));
    return v;
}

template<int ACT>
__global__ __launch_bounds__(256) void gemm_hb(
    const float* __restrict__ A, const float* __restrict__ W,
    const float* __restrict__ bias, float* __restrict__ C,
    int M, int N, int K)
{
    __shared__ float As[16][128];        // raw A (all 128 rows)  8 KB
    __shared__ float Bs[16][128];        // raw B                 8 KB
    __shared__ float Ah[16][68], Al[16][68];    // tf32 splits rows 0-63  8.5 KB
    __shared__ float Bh[16][132], Bl[16][132];  // tf32 splits all cols  16.5 KB

    const int tid = threadIdx.x;
    const int wid = tid >> 5, lane = tid & 31;
    const int m0 = blockIdx.y * 128, n0 = blockIdx.x * 128;

    // staging coords (two 16B chunks per thread)
    const int l0 = tid*2,   r0 = l0 >> 2, c0 = l0 & 3;
    const int l1 = tid*2+1, r1 = l1 >> 2, c1 = l1 & 3;
    const bool bok0 = (n0 + r0 < N);
    const bool bok1 = (n0 + r1 < N);

    // accumulators (only one set live per warp-uniform path)
    ull   accS[4][8];       // SIMT: rows 64-127
    float accT[16][4];      // tensor: m16 stripe x 16 n-atoms
    if (wid < 4) {
        #pragma unroll
        for (int i = 0; i < 4; i++)
            #pragma unroll
            for (int j = 0; j < 8; j++) accS[i][j] = 0ull;
    } else {
        #pragma unroll
        for (int na = 0; na < 16; na++)
            #pragma unroll
            for (int q = 0; q < 4; q++) accT[na][q] = 0.0f;
    }

    const int KT = K >> 4;
    #pragma unroll 1
    for (int kt = 0; kt < KT; kt++) {
        const int kb = kt << 4;
        // -------- staging (uniform, all 256 threads) --------
        {
            float4 vA0 = *reinterpret_cast<const float4*>(A + (size_t)(m0 + r0)*K + kb + c0*4);
            float4 vA1 = *reinterpret_cast<const float4*>(A + (size_t)(m0 + r1)*K + kb + c1*4);
            float4 vB0 = bok0 ? *reinterpret_cast<const float4*>(W + (size_t)(n0 + r0)*K + kb + c0*4)
                              : make_float4(0.f,0.f,0.f,0.f);
            float4 vB1 = bok1 ? *reinterpret_cast<const float4*>(W + (size_t)(n0 + r1)*K + kb + c1*4)
                              : make_float4(0.f,0.f,0.f,0.f);
            // raw A
            As[c0*4+0][r0]=vA0.x; As[c0*4+1][r0]=vA0.y; As[c0*4+2][r0]=vA0.z; As[c0*4+3][r0]=vA0.w;
            As[c1*4+0][r1]=vA1.x; As[c1*4+1][r1]=vA1.y; As[c1*4+2][r1]=vA1.z; As[c1*4+3][r1]=vA1.w;
            // raw B
            Bs[c0*4+0][r0]=vB0.x; Bs[c0*4+1][r0]=vB0.y; Bs[c0*4+2][r0]=vB0.z; Bs[c0*4+3][r0]=vB0.w;
            Bs[c1*4+0][r1]=vB1.x; Bs[c1*4+1][r1]=vB1.y; Bs[c1*4+2][r1]=vB1.z; Bs[c1*4+3][r1]=vB1.w;
            // tf32 splits: A rows 0-63 only (tid<128 <=> r0,r1 < 64)
            float h, l;
            if (r0 < 64) {
                tf32_split(vA0.x, h, l); Ah[c0*4+0][r0]=h; Al[c0*4+0][r0]=l;
                tf32_split(vA0.y, h, l); Ah[c0*4+1][r0]=h; Al[c0*4+1][r0]=l;
                tf32_split(vA0.z, h, l); Ah[c0*4+2][r0]=h; Al[c0*4+2][r0]=l;
                tf32_split(vA0.w, h, l); Ah[c0*4+3][r0]=h; Al[c0*4+3][r0]=l;
                tf32_split(vA1.x, h, l); Ah[c1*4+0][r1]=h; Al[c1*4+0][r1]=l;
                tf32_split(vA1.y, h, l); Ah[c1*4+1][r1]=h; Al[c1*4+1][r1]=l;
                tf32_split(vA1.z, h, l); Ah[c1*4+2][r1]=h; Al[c1*4+2][r1]=l;
                tf32_split(vA1.w, h, l); Ah[c1*4+3][r1]=h; Al[c1*4+3][r1]=l;
            }
            // tf32 splits: B all cols
            tf32_split(vB0.x, h, l); Bh[c0*4+0][r0]=h; Bl[c0*4+0][r0]=l;
            tf32_split(vB0.y, h, l); Bh[c0*4+1][r0]=h; Bl[c0*4+1][r0]=l;
            tf32_split(vB0.z, h, l); Bh[c0*4+2][r0]=h; Bl[c0*4+2][r0]=l;
            tf32_split(vB0.w, h, l); Bh[c0*4+3][r0]=h; Bl[c0*4+3][r0]=l;
            tf32_split(vB1.x, h, l); Bh[c1*4+0][r1]=h; Bl[c1*4+0][r1]=l;
            tf32_split(vB1.y, h, l); Bh[c1*4+1][r1]=h; Bl[c1*4+1][r1]=l;
            tf32_split(vB1.z, h, l); Bh[c1*4+2][r1]=h; Bl[c1*4+2][r1]=l;
            tf32_split(vB1.w, h, l); Bh[c1*4+3][r1]=h; Bl[c1*4+3][r1]=l;
        }
        __syncthreads();

        // -------- compute (warp-uniform divergence, no barriers inside) --------
        if (wid < 4) {
            // SIMT on rows 64-127: tid 0..127, tx in 0..15, ty2 in 0..7
            const int tx = tid & 15, ty2 = tid >> 4;
            #pragma unroll
            for (int k = 0; k < 16; k++) {
                const ulonglong2* arow = reinterpret_cast<const ulonglong2*>(&As[k][0]);
                ulonglong2 alo = arow[16 + ty2];   // rows 64+ty2*4 ..
                ulonglong2 ahi = arow[24 + ty2];   // rows 96+ty2*4 ..
                ull ap[4] = { alo.x, alo.y, ahi.x, ahi.y };
                float4 b0 = *reinterpret_cast<const float4*>(&Bs[k][tx*4]);
                float4 b1 = *reinterpret_cast<const float4*>(&Bs[k][64 + tx*4]);
                ull bd[8] = { f2dup(b0.x), f2dup(b0.y), f2dup(b0.z), f2dup(b0.w),
                              f2dup(b1.x), f2dup(b1.y), f2dup(b1.z), f2dup(b1.w) };
                #pragma unroll
                for (int i = 0; i < 4; i++)
                    #pragma unroll
                    for (int j = 0; j < 8; j++)
                        ffma2(accS[i][j], ap[i], bd[j]);
            }
        } else {
            // tensor warp w (0-3): rows w*16 .. w*16+15, all 128 cols
            const int w = wid - 4;
            const int l4 = lane & 3, l2 = lane >> 2;
            const int mm = w*16 + l2;
            #pragma unroll
            for (int k8 = 0; k8 < 2; k8++) {
                const int kk = k8*8 + l4;
                uint32_t ah[4], al[4];
                ah[0] = __float_as_uint(Ah[kk][mm]);
                ah[1] = __float_as_uint(Ah[kk][mm+8]);
                ah[2] = __float_as_uint(Ah[kk+4][mm]);
                ah[3] = __float_as_uint(Ah[kk+4][mm+8]);
                al[0] = __float_as_uint(Al[kk][mm]);
                al[1] = __float_as_uint(Al[kk][mm+8]);
                al[2] = __float_as_uint(Al[kk+4][mm]);
                al[3] = __float_as_uint(Al[kk+4][mm+8]);
                #pragma unroll
                for (int na = 0; na < 16; na++) {
                    const int nn = na*8 + l2;
                    uint32_t bh[2], bl[2];
                    bh[0] = __float_as_uint(Bh[kk][nn]);
                    bh[1] = __float_as_uint(Bh[kk+4][nn]);
                    bl[0] = __float_as_uint(Bl[kk][nn]);
                    bl[1] = __float_as_uint(Bl[kk+4][nn]);
                    mma_tf32(accT[na], ah, bh);
                    mma_tf32(accT[na], ah, bl);
                    mma_tf32(accT[na], al, bh);
                }
            }
        }
        __syncthreads();
    }

    // -------- epilogue --------
    if (wid < 4) {
        const int tx = tid & 15, ty2 = tid >> 4;
        int cols[8];
        #pragma unroll
        for (int j = 0; j < 4; j++) { cols[j] = n0 + tx*4 + j; cols[j+4] = n0 + 64 + tx*4 + j; }
        float bcol[8];
        #pragma unroll
        for (int j = 0; j < 8; j++) bcol[j] = (cols[j] < N) ? bias[cols[j]] : 0.0f;
        #pragma unroll
        for (int ip = 0; ip < 4; ip++) {
            int rlo = m0 + ((ip < 2) ? (64 + ty2*4 + ip*2) : (96 + ty2*4 + (ip-2)*2));
            int rhi = rlo + 1;
            #pragma unroll
            for (int j = 0; j < 8; j++) {
                if (cols[j] < N) {
                    float vlo, vhi;
                    f2unpack(accS[ip][j], vlo, vhi);
                    C[(size_t)rlo*N + cols[j]] = actf<ACT>(vlo + bcol[j]);
                    C[(size_t)rhi*N + cols[j]] = actf<ACT>(vhi + bcol[j]);
                }
            }
        }
    } else {
        const int w = wid - 4;
        const int l4 = lane & 3, l2 = lane >> 2;
        const int row0 = m0 + w*16 + l2;
        #pragma unroll
        for (int na = 0; na < 16; na++) {
            int col0 = n0 + na*8 + 2*l4;
            #pragma unroll
            for (int half = 0; half < 2; half++) {
                int row = row0 + half*8;
                #pragma unroll
                for (int cq = 0; cq < 2; cq++) {
                    int col = col0 + cq;
                    if (col < N)
                        C[(size_t)row*N + col] = actf<ACT>(accT[na][half*2 + cq] + bias[col]);
                }
            }
        }
    }
}

// ---------------- z stats ----------------
__global__ void zstats_kernel(const float* __restrict__ eps, float* __restrict__ out)
{
    int i = blockIdx.x*blockDim.x + threadIdx.x;
    if (i >= BB*LDIM) return;
    int s = i >> 4, k = i & 15;
    float mean = g_ms[s*2*LDIM + k];
    float logs = g_ms[s*2*LDIM + LDIM + k];
    float sd = expf(logs) + 1e-6f;
    out[OFF_MEAN + i] = mean;
    out[OFF_STD  + i] = sd;
    g_z[i] = mean + eps[i]*sd;
}

// ---------------- base_c ----------------
__global__ void bc_kernel(const float* __restrict__ emb, const int* __restrict__ cond,
                          const float* __restrict__ cwc)
{
    __shared__ float cw[CDIM*CDIM];
    int tid = threadIdx.x;
    for (int i = tid; i < CDIM*CDIM; i += 256) cw[i] = cwc[i];
    __syncthreads();
    int idx = blockIdx.x*256 + tid;
    if (idx >= BB*CDIM) return;
    int s = idx >> 5, j = idx & 31;
    const float* er = emb + cond[s]*CDIM;
    float a = 0.0f;
    #pragma unroll
    for (int k = 0; k < CDIM; k++) a += er[k]*cw[j*CDIM + k];
    g_bc[idx] = a;
}

// ---------------- hypernet stage 1 ----------------
__global__ void hyper1_kernel(const float* __restrict__ hw1, const float* __restrict__ hb1,
                              const float* __restrict__ hw2, const float* __restrict__ hb2)
{
    __shared__ float x1[OHID];
    int t = blockIdx.x, j = threadIdx.x;
    float tv = 10.0f - 0.3125f * (float)t;
    x1[j] = tanhf(tv*hw1[j] + hb1[j]);
    __syncthreads();
    float a = hb2[j];
    #pragma unroll 8
    for (int k = 0; k < OHID; k++) a += x1[k]*hw2[j*OHID + k];
    g_x2[t*OHID + j] = tanhf(a);
}

// ---------------- hypernet stage 2 ----------------
#define H2_ROWS 12
__global__ void hyper2_kernel(const float* __restrict__ hw3, const float* __restrict__ hb3)
{
    __shared__ float rows[H2_ROWS*257];
    __shared__ float x2s[NTT*257];
    int tid = threadIdx.x;
    int r0 = blockIdx.x * H2_ROWS;
    for (int i = tid; i < H2_ROWS*256; i += 256) {
        int r = i >> 8, k = i & 255;
        if (r0 + r < P3SZ) rows[r*257 + k] = hw3[(size_t)(r0 + r)*256 + k];
    }
    for (int i = tid; i < NTT*256; i += 256) {
        int t = i >> 8, k = i & 255;
        x2s[t*257 + k] = g_x2[i];
    }
    __syncthreads();
    for (int o = tid; o < H2_ROWS*NTT; o += 256) {
        int r = o / NTT, t = o - r*NTT;
        if (r0 + r >= P3SZ) continue;
        float a = hb3[r0 + r];
        #pragma unroll 8
        for (int k = 0; k < 256; k++) a += rows[r*257 + k]*x2s[t*257 + k];
        g_p[t*P3SZ + r0 + r] = a;
    }
}

// ---------------- hypernet stage 3 ----------------
__global__ void hyper3_kernel()
{
    int t = blockIdx.x;
    int j = threadIdx.x;
    const float* p = g_p + t*P3SZ;
    int sub = j >> 5, rem = j & 31, j4 = rem >> 2, q = rem & 3;
    float wu = 0.0f;
    #pragma unroll
    for (int k = 0; k < LDIM; k++) {
        float Wv = p[j*LDIM + k];
        float Uv = p[4096 + j*LDIM + k] * sigm(p[8192 + j*LDIM + k]);
        wu += Wv*Uv;
        reinterpret_cast<float*>(&g_Wp[((t*16 + k)*8 + j4)*8 + sub])[q] = Wv;
        reinterpret_cast<float*>(&g_Up[((t*16 + k)*8 + j4)*8 + sub])[q] = Uv;
    }
    reinterpret_cast<float*>(&g_Bp [t*64 + j4*8 + sub])[q] = p[12288 + j];
    reinterpret_cast<float*>(&g_wup[t*64 + j4*8 + sub])[q] = wu;
}

__global__ void initxp_kernel(float* out) { out[OFF_XP] = 0.0f; }

// ---------------- CNF main kernel: EXACT R8 kernel ----------------
#define SPT 2

__global__ __launch_bounds__(256, 1) void cnf_kernel(
    const float* __restrict__ cwz, const float* __restrict__ cbz,
    const float* __restrict__ cbc, float* __restrict__ out)
{
    __shared__ float4 shW[16*64];
    __shared__ float4 shU[16*64];
    __shared__ float4 shB[64];
    __shared__ float4 shwu[64];
    __shared__ float  shcwz[16*32];
    __shared__ float  shcb[32];
    __shared__ float  redbuf[32];

    const int tid  = threadIdx.x;
    const int sub  = tid & 7;
    const int s0   = blockIdx.x*64 + (tid >> 3);
    const unsigned lane = tid & 31;
    const int gbase = lane & ~7;

    for (int i = tid; i < 512; i += 256) {
        int j = i >> 4, k = i & 15;
        shcwz[k*32 + j] = cwz[i];
    }
    if (tid < 32) shcb[tid] = cbz[tid] + cbc[tid];

    float z[SPT][16], zs[SPT][16], accum[SPT][16];
    float bc[SPT][4];
    #pragma unroll
    for (int s = 0; s < SPT; s++) {
        int sg = s0 + s*32;
        #pragma unroll
        for (int k = 0; k < 16; k++) z[s][k] = g_z[sg*16 + k];
        float4 b = *reinterpret_cast<const float4*>(&g_bc[sg*32 + sub*4]);
        bc[s][0] = b.x; bc[s][1] = b.y; bc[s][2] = b.z; bc[s][3] = b.w;
    }
    __syncthreads();
    float cb[4];
    #pragma unroll
    for (int q = 0; q < 4; q++) cb[q] = shcb[sub*4 + q];

    const float h   = -0.625f;
    const float h6  = -0.625f/6.0f;
    const float k2f = 1.0f + 0.5f*h;
    const float k3f = 1.0f + 0.5f*h*k2f;
    const float k4f = 1.0f + h*k3f;
    const float gfac = 1.0f + h6*(1.0f + 2.0f*k2f + 2.0f*k3f + k4f);
    const float inv = 1.0f/256.0f;

    float lp[SPT] = {0.0f, 0.0f};
    float gpow = 1.0f;

    #pragma unroll 1
    for (int step = 0; step < 16; step++) {
        float lacc[SPT] = {0.0f, 0.0f};
        #pragma unroll
        for (int s = 0; s < SPT; s++)
            #pragma unroll
            for (int k = 0; k < 16; k++) { accum[s][k] = 0.0f; zs[s][k] = z[s][k]; }

        #pragma unroll 1
        for (int st = 0; st < 4; st++) {
            int tidx = 2*step + ((st == 0) ? 0 : ((st == 3) ? 2 : 1));
            float sc = gpow * ((st == 0) ? 1.0f : (st == 1) ? k2f : (st == 2) ? k3f : k4f);

            __syncthreads();
            {
                const float4* srcW = g_Wp + tidx*1024;
                const float4* srcU = g_Up + tidx*1024;
                #pragma unroll
                for (int i = 0; i < 4; i++) shW[tid + i*256] = srcW[tid + i*256];
                #pragma unroll
                for (int i = 0; i < 4; i++) shU[tid + i*256] = srcU[tid + i*256];
                if (tid < 64)                   shB[tid]      = g_Bp [tidx*64 + tid];
                else if (tid < 128)             shwu[tid-64]  = g_wup[tidx*64 + tid - 64];
            }
            __syncthreads();

            float a[SPT][4];
            #pragma unroll
            for (int s = 0; s < SPT; s++)
                #pragma unroll
                for (int q = 0; q < 4; q++) a[s][q] = sc*bc[s][q] + cb[q];
            #pragma unroll
            for (int k = 0; k < 16; k++) {
                float4 cw = *reinterpret_cast<const float4*>(&shcwz[k*32 + sub*4]);
                #pragma unroll
                for (int s = 0; s < SPT; s++) {
                    a[s][0] += zs[s][k]*cw.x; a[s][1] += zs[s][k]*cw.y;
                    a[s][2] += zs[s][k]*cw.z; a[s][3] += zs[s][k]*cw.w;
                }
            }

            ull w2[SPT][16];
            #pragma unroll
            for (int s = 0; s < SPT; s++)
                #pragma unroll
                for (int p = 0; p < 16; p++) w2[s][p] = 0ull;

            const ulonglong2* shWu = reinterpret_cast<const ulonglong2*>(shW);
            #pragma unroll
            for (int k = 0; k < 16; k++) {
                ull zd[SPT];
                #pragma unroll
                for (int s = 0; s < SPT; s++) {
                    float a1 = __shfl_sync(0xffffffffu, a[s][k & 3], gbase + (k >> 2));
                    float a2 = __shfl_sync(0xffffffffu, a[s][k & 3], gbase + 4 + (k >> 2));
                    zd[s] = f2dup(tanha(a1) * sigma_fast(a2));
                }
                #pragma unroll
                for (int j4 = 0; j4 < 8; j4++) {
                    ulonglong2 wv = shWu[(k*8 + j4)*8 + sub];
                    #pragma unroll
                    for (int s = 0; s < SPT; s++) {
                        ffma2(w2[s][j4*2+0], zd[s], wv.x);
                        ffma2(w2[s][j4*2+1], zd[s], wv.y);
                    }
                }
            }

            float tr[SPT] = {0.0f, 0.0f};
            #pragma unroll
            for (int j4 = 0; j4 < 8; j4++) {
                float4 bv  = shB[j4*8 + sub];
                float4 wuv = shwu[j4*8 + sub];
                #pragma unroll
                for (int s = 0; s < SPT; s++) {
                    float l0, h0, l1, h1;
                    f2unpack(w2[s][j4*2+0], l0, h0);
                    f2unpack(w2[s][j4*2+1], l1, h1);
                    float t0 = tanha(l0 + bv.x); tr[s] += (1.0f - t0*t0)*wuv.x;
                    float t1 = tanha(h0 + bv.y); tr[s] += (1.0f - t1*t1)*wuv.y;
                    float t2 = tanha(l1 + bv.z); tr[s] += (1.0f - t2*t2)*wuv.z;
                    float t3 = tanha(h1 + bv.w); tr[s] += (1.0f - t3*t3)*wuv.w;
                    w2[s][j4*2+0] = f2pack(t0, t1);
                    w2[s][j4*2+1] = f2pack(t2, t3);
                }
            }

            float wgt = (st == 0 || st == 3) ? 1.0f : 2.0f;
            float cf  = (st < 2) ? 0.5f*h : h;
            const ulonglong2* shUu = reinterpret_cast<const ulonglong2*>(shU);
            #pragma unroll
            for (int k = 0; k < 16; k++) {
                ull da[SPT], db[SPT];
                #pragma unroll
                for (int s = 0; s < SPT; s++) { da[s] = 0ull; db[s] = 0ull; }
                #pragma unroll
                for (int j4 = 0; j4 < 8; j4++) {
                    ulonglong2 uv = shUu[(k*8 + j4)*8 + sub];
                    #pragma unroll
                    for (int s = 0; s < SPT; s++) {
                        ffma2(da[s], w2[s][j4*2+0], uv.x);
                        ffma2(db[s], w2[s][j4*2+1], uv.y);
                    }
                }
                #pragma unroll
                for (int s = 0; s < SPT; s++) {
                    float lo, hi, lo2, hi2;
                    f2unpack(da[s], lo, hi);
                    f2unpack(db[s], lo2, hi2);
                    float d = (lo + lo2) + (hi + hi2);
                    d += __shfl_xor_sync(0xffffffffu, d, 1);
                    d += __shfl_xor_sync(0xffffffffu, d, 2);
                    d += __shfl_xor_sync(0xffffffffu, d, 4);
                    d *= inv;
                    accum[s][k] += wgt*d;
                    if (st < 3) zs[s][k] = z[s][k] + cf*d;
                }
            }

            #pragma unroll
            for (int s = 0; s < SPT; s++) {
                float t = tr[s];
                t += __shfl_xor_sync(0xffffffffu, t, 1);
                t += __shfl_xor_sync(0xffffffffu, t, 2);
                t += __shfl_xor_sync(0xffffffffu, t, 4);
                lacc[s] += wgt * (-t*inv);
            }
        }

        #pragma unroll
        for (int s = 0; s < SPT; s++) {
            #pragma unroll
            for (int k = 0; k < 16; k++) z[s][k] += h6*accum[s][k];
            lp[s] += h6*lacc[s];
        }
        gpow *= gfac;
    }

    float lx = 0.0f;
    #pragma unroll
    for (int s = 0; s < SPT; s++) {
        float sq = 0.0f;
        #pragma unroll
        for (int k = 0; k < 16; k++) sq += z[s][k]*z[s][k];
        lx += -0.5f*(16.0f*1.8378770664093453f + sq) - lp[s];
    }

    __syncthreads();
    if (sub == 0) redbuf[tid >> 3] = lx;
    __syncthreads();
    if (tid < 32) {
        float v = redbuf[tid];
        #pragma unroll
        for (int m = 16; m >= 1; m >>= 1) v += __shfl_xor_sync(0xffffffffu, v, m);
        if (tid == 0) atomicAdd(&out[OFF_XP], v * (1.0f/(float)BB));
    }
}

// ---------------- launch ----------------
extern "C" void kernel_launch(void* const* d_in, const int* in_sizes, int n_in,
                              void* d_out, int out_size)
{
    const float* input = (const float*)d_in[0];
    const float* eps   = (const float*)d_in[1];
    const float* ew0   = (const float*)d_in[2];
    const float* eb0   = (const float*)d_in[3];
    const float* ew1   = (const float*)d_in[4];
    const float* eb1   = (const float*)d_in[5];
    const float* ew2   = (const float*)d_in[6];
    const float* eb2   = (const float*)d_in[7];
    const float* dw0   = (const float*)d_in[8];
    const float* db0   = (const float*)d_in[9];
    const float* dw1   = (const float*)d_in[10];
    const float* db1   = (const float*)d_in[11];
    const float* dw2   = (const float*)d_in[12];
    const float* db2   = (const float*)d_in[13];
    const float* emb   = (const float*)d_in[14];
    const float* cwz   = (const float*)d_in[15];
    const float* cbz   = (const float*)d_in[16];
    const float* cwc   = (const float*)d_in[17];
    const float* cbc   = (const float*)d_in[18];
    const float* hw1   = (const float*)d_in[19];
    const float* hb1   = (const float*)d_in[20];
    const float* hw2   = (const float*)d_in[21];
    const float* hb2   = (const float*)d_in[22];
    const float* hw3   = (const float*)d_in[23];
    const float* hb3   = (const float*)d_in[24];
    const int*   cond  = (const int*)  d_in[25];
    float* out = (float*)d_out;

    float *bufA, *bufB, *ms, *z;
    cudaGetSymbolAddress((void**)&bufA, g_bufA);
    cudaGetSymbolAddress((void**)&bufB, g_bufB);
    cudaGetSymbolAddress((void**)&ms,   g_ms);
    cudaGetSymbolAddress((void**)&z,    g_z);

    dim3 blk(256);

    // (1-3) CNF precompute prologue
    bc_kernel<<<(BB*CDIM)/256, 256>>>(emb, cond, cwc);
    hyper1_kernel<<<NTT, 256>>>(hw1, hb1, hw2, hb2);
    hyper2_kernel<<<(P3SZ + H2_ROWS - 1)/H2_ROWS, 256>>>(hw3, hb3);

    // (4) big GEMM in profiled slot
    gemm_hb<ACT_ELU ><<<dim3(4, 64), blk>>>(input, ew0, eb0, bufA, BB, HID, DIN);

    hyper3_kernel<<<NTT, 256>>>();

    gemm_hb<ACT_TANH><<<dim3(4, 64), blk>>>(bufA,  ew1, eb1, bufB, BB, HID, HID);
    gemm_hb<ACT_NONE><<<dim3(1, 64), blk>>>(bufB,  ew2, eb2, ms,   BB, 2*LDIM, HID);
    zstats_kernel<<<(BB*LDIM)/256, 256>>>(eps, out);

    gemm_hb<ACT_ELU ><<<dim3(4, 64), blk>>>(z,    dw0, db0, bufA, BB, HID, LDIM);
    gemm_hb<ACT_TANH><<<dim3(4, 64), blk>>>(bufA, dw1, db1, bufB, BB, HID, HID);
    gemm_hb<ACT_SIG ><<<dim3(7, 64), blk>>>(bufB, dw2, db2, out,  BB, DIN, HID);

    initxp_kernel<<<1, 1>>>(out);

    // CNF main
    cnf_kernel<<<BB/(32*SPT), 256>>>(cwz, cbz, cbc, out);
}

// round 16
// speedup vs baseline: 1.0314x; 1.0314x over previous
#include <cuda_runtime.h>
#include <math.h>
#include <stdint.h>

// ---------------- problem constants ----------------
#define BB    8192
#define DIN   784
#define HID   512
#define LDIM  16
#define CDIM  32
#define OHID  256
#define WIDN  256
#define P3SZ  (3*WIDN*LDIM + WIDN)   // 12544
#define NTT   33

#define OFF_XP   (BB*DIN)
#define OFF_MEAN (OFF_XP + 1)
#define OFF_STD  (OFF_MEAN + BB*LDIM)

typedef unsigned long long ull;

// ---------------- f32x2 helpers ----------------
__device__ __forceinline__ ull f2dup(float x) {
    ull r; asm("mov.b64 %0, {%1, %1};" : "=l"(r) : "f"(x)); return r;
}
__device__ __forceinline__ ull f2pack(float x, float y) {
    ull r; asm("mov.b64 %0, {%1, %2};" : "=l"(r) : "f"(x), "f"(y)); return r;
}
__device__ __forceinline__ void f2unpack(ull v, float& x, float& y) {
    asm("mov.b64 {%0, %1}, %2;" : "=f"(x), "=f"(y) : "l"(v));
}
__device__ __forceinline__ void ffma2(ull& d, ull a, ull b) {
    asm("fma.rn.f32x2 %0, %1, %2, %0;" : "+l"(d) : "l"(a), "l"(b));
}

// ---------------- fast transcendentals (CNF only) ----------------
__device__ __forceinline__ float tanha(float x) {
    float r; asm("tanh.approx.f32 %0, %1;" : "=f"(r) : "f"(x)); return r;
}
__device__ __forceinline__ float sigma_fast(float x) {
    float t = -1.4426950408889634f * x;
    float e; asm("ex2.approx.f32 %0, %1;" : "=f"(e) : "f"(t));
    float d = 1.0f + e;
    float r; asm("rcp.approx.f32 %0, %1;" : "=f"(r) : "f"(d));
    return r;
}

__device__ __forceinline__ float sigm(float x) { return 1.0f/(1.0f+expf(-x)); }

// ---------------- device scratch ----------------
__device__ float  g_bufA[BB*HID];
__device__ float  g_bufB[BB*HID];
__device__ float  g_ms[BB*2*LDIM];
__device__ float  g_z[BB*LDIM];
__device__ float  g_bc[BB*CDIM];
__device__ float  g_x2[NTT*OHID];
__device__ float  g_p[NTT*P3SZ];
__device__ float4 g_Wp[NTT*16*64];
__device__ float4 g_Up[NTT*16*64];
__device__ float4 g_Bp[NTT*64];
__device__ float4 g_wup[NTT*64];

enum { ACT_NONE=0, ACT_ELU=1, ACT_TANH=2, ACT_SIG=3 };

// ================= shared-memory layouts =================
struct CnfSmem {
    float4 shW[1024];     // 16 KB
    float4 shU[1024];     // 16 KB
    float4 shB[64];
    float4 shwu[64];
    float  shcwz[512];
    float  shcb[32];
    float  redbuf[32];
};                         // ~37 KB
struct GemmSmem {
    float As[16][128];
    float Bs[16][128];
};                         // 16 KB
union FusedSmem { CnfSmem c; GemmSmem g; };

// ================= R8 SIMT GEMM body (device fn) =================
template<int ACT>
__device__ __forceinline__ void gemm_body(
    GemmSmem& sm,
    const float* __restrict__ A, const float* __restrict__ W,
    const float* __restrict__ bias, float* __restrict__ C,
    int M, int N, int K, int bx, int by)
{
    float (*As)[128] = sm.As;
    float (*Bs)[128] = sm.Bs;
    const int tid = threadIdx.x;
    const int tx = tid & 15, ty = tid >> 4;
    const int m0 = by * 128, n0 = bx * 128;

    ull acc2[4][8];
    #pragma unroll
    for (int i = 0; i < 4; i++)
        #pragma unroll
        for (int j = 0; j < 8; j++) acc2[i][j] = 0ull;

    #pragma unroll 1
    for (int k0 = 0; k0 < K; k0 += 16) {
        #pragma unroll
        for (int q = 0; q < 2; q++) {
            int l = tid*2 + q;
            int r = l >> 2, c = l & 3;
            float4 v = *reinterpret_cast<const float4*>(A + (size_t)(m0 + r)*K + k0 + c*4);
            As[c*4+0][r] = v.x; As[c*4+1][r] = v.y; As[c*4+2][r] = v.z; As[c*4+3][r] = v.w;
        }
        #pragma unroll
        for (int q = 0; q < 2; q++) {
            int l = tid*2 + q;
            int r = l >> 2, c = l & 3;
            float4 v = make_float4(0.f, 0.f, 0.f, 0.f);
            if (n0 + r < N)
                v = *reinterpret_cast<const float4*>(W + (size_t)(n0 + r)*K + k0 + c*4);
            Bs[c*4+0][r] = v.x; Bs[c*4+1][r] = v.y; Bs[c*4+2][r] = v.z; Bs[c*4+3][r] = v.w;
        }
        __syncthreads();
        #pragma unroll
        for (int k = 0; k < 16; k++) {
            const ulonglong2* arow = reinterpret_cast<const ulonglong2*>(&As[k][0]);
            ulonglong2 alo = arow[ty];
            ulonglong2 ahi = arow[16 + ty];
            ull ap[4] = { alo.x, alo.y, ahi.x, ahi.y };
            float4 b0 = *reinterpret_cast<const float4*>(&Bs[k][tx*4]);
            float4 b1 = *reinterpret_cast<const float4*>(&Bs[k][64 + tx*4]);
            ull bd[8] = { f2dup(b0.x), f2dup(b0.y), f2dup(b0.z), f2dup(b0.w),
                          f2dup(b1.x), f2dup(b1.y), f2dup(b1.z), f2dup(b1.w) };
            #pragma unroll
            for (int i = 0; i < 4; i++)
                #pragma unroll
                for (int j = 0; j < 8; j++)
                    ffma2(acc2[i][j], ap[i], bd[j]);
        }
        __syncthreads();
    }

    int cols[8];
    #pragma unroll
    for (int j = 0; j < 4; j++) { cols[j] = n0 + tx*4 + j; cols[j+4] = n0 + 64 + tx*4 + j; }
    float bcol[8];
    #pragma unroll
    for (int j = 0; j < 8; j++) bcol[j] = (cols[j] < N) ? bias[cols[j]] : 0.0f;

    #pragma unroll
    for (int ip = 0; ip < 4; ip++) {
        int rlo = m0 + ((ip < 2) ? (ty*4 + ip*2) : (64 + ty*4 + (ip-2)*2));
        int rhi = rlo + 1;
        #pragma unroll
        for (int j = 0; j < 8; j++) {
            if (cols[j] < N) {
                float vlo, vhi;
                f2unpack(acc2[ip][j], vlo, vhi);
                vlo += bcol[j]; vhi += bcol[j];
                if (ACT == ACT_ELU)  { vlo = (vlo > 0.0f) ? vlo : expm1f(vlo);
                                       vhi = (vhi > 0.0f) ? vhi : expm1f(vhi); }
                if (ACT == ACT_TANH) { vlo = tanhf(vlo); vhi = tanhf(vhi); }
                if (ACT == ACT_SIG)  { vlo = 1.0f/(1.0f+expf(-vlo));
                                       vhi = 1.0f/(1.0f+expf(-vhi)); }
                C[(size_t)rlo*N + cols[j]] = vlo;
                C[(size_t)rhi*N + cols[j]] = vhi;
            }
        }
    }
}

// standalone GEMM (e1,e2,e3,d1,d2) — exact R8 behavior
template<int ACT>
__global__ __launch_bounds__(256) void gemm_nt(
    const float* __restrict__ A, const float* __restrict__ W,
    const float* __restrict__ bias, float* __restrict__ C,
    int M, int N, int K)
{
    __shared__ GemmSmem sm;
    gemm_body<ACT>(sm, A, W, bias, C, M, N, K, blockIdx.x, blockIdx.y);
}

// ================= R8 CNF body (device fn) =================
#define SPT 2

__device__ __forceinline__ void cnf_body(
    CnfSmem& sm, int bid,
    const float* __restrict__ cwz, const float* __restrict__ cbz,
    const float* __restrict__ cbc, float* __restrict__ out)
{
    float4* shW   = sm.shW;
    float4* shU   = sm.shU;
    float4* shB   = sm.shB;
    float4* shwu  = sm.shwu;
    float*  shcwz = sm.shcwz;
    float*  shcb  = sm.shcb;
    float*  redbuf= sm.redbuf;

    const int tid  = threadIdx.x;
    const int sub  = tid & 7;
    const int s0   = bid*64 + (tid >> 3);
    const unsigned lane = tid & 31;
    const int gbase = lane & ~7;

    for (int i = tid; i < 512; i += 256) {
        int j = i >> 4, k = i & 15;
        shcwz[k*32 + j] = cwz[i];
    }
    if (tid < 32) shcb[tid] = cbz[tid] + cbc[tid];

    float z[SPT][16], zs[SPT][16], accum[SPT][16];
    float bc[SPT][4];
    #pragma unroll
    for (int s = 0; s < SPT; s++) {
        int sg = s0 + s*32;
        #pragma unroll
        for (int k = 0; k < 16; k++) z[s][k] = g_z[sg*16 + k];
        float4 b = *reinterpret_cast<const float4*>(&g_bc[sg*32 + sub*4]);
        bc[s][0] = b.x; bc[s][1] = b.y; bc[s][2] = b.z; bc[s][3] = b.w;
    }
    __syncthreads();
    float cb[4];
    #pragma unroll
    for (int q = 0; q < 4; q++) cb[q] = shcb[sub*4 + q];

    const float h   = -0.625f;
    const float h6  = -0.625f/6.0f;
    const float k2f = 1.0f + 0.5f*h;
    const float k3f = 1.0f + 0.5f*h*k2f;
    const float k4f = 1.0f + h*k3f;
    const float gfac = 1.0f + h6*(1.0f + 2.0f*k2f + 2.0f*k3f + k4f);
    const float inv = 1.0f/256.0f;

    float lp[SPT] = {0.0f, 0.0f};
    float gpow = 1.0f;

    #pragma unroll 1
    for (int step = 0; step < 16; step++) {
        float lacc[SPT] = {0.0f, 0.0f};
        #pragma unroll
        for (int s = 0; s < SPT; s++)
            #pragma unroll
            for (int k = 0; k < 16; k++) { accum[s][k] = 0.0f; zs[s][k] = z[s][k]; }

        #pragma unroll 1
        for (int st = 0; st < 4; st++) {
            int tidx = 2*step + ((st == 0) ? 0 : ((st == 3) ? 2 : 1));
            float sc = gpow * ((st == 0) ? 1.0f : (st == 1) ? k2f : (st == 2) ? k3f : k4f);

            __syncthreads();
            {
                const float4* srcW = g_Wp + tidx*1024;
                const float4* srcU = g_Up + tidx*1024;
                #pragma unroll
                for (int i = 0; i < 4; i++) shW[tid + i*256] = srcW[tid + i*256];
                #pragma unroll
                for (int i = 0; i < 4; i++) shU[tid + i*256] = srcU[tid + i*256];
                if (tid < 64)                   shB[tid]      = g_Bp [tidx*64 + tid];
                else if (tid < 128)             shwu[tid-64]  = g_wup[tidx*64 + tid - 64];
            }
            __syncthreads();

            float a[SPT][4];
            #pragma unroll
            for (int s = 0; s < SPT; s++)
                #pragma unroll
                for (int q = 0; q < 4; q++) a[s][q] = sc*bc[s][q] + cb[q];
            #pragma unroll
            for (int k = 0; k < 16; k++) {
                float4 cw = *reinterpret_cast<const float4*>(&shcwz[k*32 + sub*4]);
                #pragma unroll
                for (int s = 0; s < SPT; s++) {
                    a[s][0] += zs[s][k]*cw.x; a[s][1] += zs[s][k]*cw.y;
                    a[s][2] += zs[s][k]*cw.z; a[s][3] += zs[s][k]*cw.w;
                }
            }

            ull w2[SPT][16];
            #pragma unroll
            for (int s = 0; s < SPT; s++)
                #pragma unroll
                for (int p = 0; p < 16; p++) w2[s][p] = 0ull;

            const ulonglong2* shWu = reinterpret_cast<const ulonglong2*>(shW);
            #pragma unroll
            for (int k = 0; k < 16; k++) {
                ull zd[SPT];
                #pragma unroll
                for (int s = 0; s < SPT; s++) {
                    float a1 = __shfl_sync(0xffffffffu, a[s][k & 3], gbase + (k >> 2));
                    float a2 = __shfl_sync(0xffffffffu, a[s][k & 3], gbase + 4 + (k >> 2));
                    zd[s] = f2dup(tanha(a1) * sigma_fast(a2));
                }
                #pragma unroll
                for (int j4 = 0; j4 < 8; j4++) {
                    ulonglong2 wv = shWu[(k*8 + j4)*8 + sub];
                    #pragma unroll
                    for (int s = 0; s < SPT; s++) {
                        ffma2(w2[s][j4*2+0], zd[s], wv.x);
                        ffma2(w2[s][j4*2+1], zd[s], wv.y);
                    }
                }
            }

            float tr[SPT] = {0.0f, 0.0f};
            #pragma unroll
            for (int j4 = 0; j4 < 8; j4++) {
                float4 bv  = shB[j4*8 + sub];
                float4 wuv = shwu[j4*8 + sub];
                #pragma unroll
                for (int s = 0; s < SPT; s++) {
                    float l0, h0, l1, h1;
                    f2unpack(w2[s][j4*2+0], l0, h0);
                    f2unpack(w2[s][j4*2+1], l1, h1);
                    float t0 = tanha(l0 + bv.x); tr[s] += (1.0f - t0*t0)*wuv.x;
                    float t1 = tanha(h0 + bv.y); tr[s] += (1.0f - t1*t1)*wuv.y;
                    float t2 = tanha(l1 + bv.z); tr[s] += (1.0f - t2*t2)*wuv.z;
                    float t3 = tanha(h1 + bv.w); tr[s] += (1.0f - t3*t3)*wuv.w;
                    w2[s][j4*2+0] = f2pack(t0, t1);
                    w2[s][j4*2+1] = f2pack(t2, t3);
                }
            }

            float wgt = (st == 0 || st == 3) ? 1.0f : 2.0f;
            float cf  = (st < 2) ? 0.5f*h : h;
            const ulonglong2* shUu = reinterpret_cast<const ulonglong2*>(shU);
            #pragma unroll
            for (int k = 0; k < 16; k++) {
                ull da[SPT], db[SPT];
                #pragma unroll
                for (int s = 0; s < SPT; s++) { da[s] = 0ull; db[s] = 0ull; }
                #pragma unroll
                for (int j4 = 0; j4 < 8; j4++) {
                    ulonglong2 uv = shUu[(k*8 + j4)*8 + sub];
                    #pragma unroll
                    for (int s = 0; s < SPT; s++) {
                        ffma2(da[s], w2[s][j4*2+0], uv.x);
                        ffma2(db[s], w2[s][j4*2+1], uv.y);
                    }
                }
                #pragma unroll
                for (int s = 0; s < SPT; s++) {
                    float lo, hi, lo2, hi2;
                    f2unpack(da[s], lo, hi);
                    f2unpack(db[s], lo2, hi2);
                    float d = (lo + lo2) + (hi + hi2);
                    d += __shfl_xor_sync(0xffffffffu, d, 1);
                    d += __shfl_xor_sync(0xffffffffu, d, 2);
                    d += __shfl_xor_sync(0xffffffffu, d, 4);
                    d *= inv;
                    accum[s][k] += wgt*d;
                    if (st < 3) zs[s][k] = z[s][k] + cf*d;
                }
            }

            #pragma unroll
            for (int s = 0; s < SPT; s++) {
                float t = tr[s];
                t += __shfl_xor_sync(0xffffffffu, t, 1);
                t += __shfl_xor_sync(0xffffffffu, t, 2);
                t += __shfl_xor_sync(0xffffffffu, t, 4);
                lacc[s] += wgt * (-t*inv);
            }
        }

        #pragma unroll
        for (int s = 0; s < SPT; s++) {
            #pragma unroll
            for (int k = 0; k < 16; k++) z[s][k] += h6*accum[s][k];
            lp[s] += h6*lacc[s];
        }
        gpow *= gfac;
    }

    float lx = 0.0f;
    #pragma unroll
    for (int s = 0; s < SPT; s++) {
        float sq = 0.0f;
        #pragma unroll
        for (int k = 0; k < 16; k++) sq += z[s][k]*z[s][k];
        lx += -0.5f*(16.0f*1.8378770664093453f + sq) - lp[s];
    }

    __syncthreads();
    if (sub == 0) redbuf[tid >> 3] = lx;
    __syncthreads();
    if (tid < 32) {
        float v = redbuf[tid];
        #pragma unroll
        for (int m = 16; m >= 1; m >>= 1) v += __shfl_xor_sync(0xffffffffu, v, m);
        if (tid == 0) atomicAdd(&out[OFF_XP], v * (1.0f/(float)BB));
    }
}

// ================= fused d3 + CNF kernel =================
// 576 blocks: bid<512 && (bid&3)==3 -> CNF block (128 total, interleaved 1:3)
// otherwise -> d3 GEMM block (448 total)
__global__ __launch_bounds__(256) void fused_d3_cnf(
    const float* __restrict__ A, const float* __restrict__ W,
    const float* __restrict__ bias, float* __restrict__ C,
    const float* __restrict__ cwz, const float* __restrict__ cbz,
    const float* __restrict__ cbc, float* __restrict__ out)
{
    __shared__ FusedSmem sm;
    const int bid = blockIdx.x;
    const bool iscnf = (bid < 512) && ((bid & 3) == 3);
    if (iscnf) {
        cnf_body(sm.c, bid >> 2, cwz, cbz, cbc, out);
    } else {
        int d3 = (bid < 512) ? (bid - ((bid + 1) >> 2)) : (bid - 128);
        int bx = d3 % 7, by = d3 / 7;
        gemm_body<ACT_SIG>(sm.g, A, W, bias, C, BB, DIN, HID, bx, by);
    }
}

// ---------------- z stats (+ zero x_probs accumulator) ----------------
__global__ void zstats_kernel(const float* __restrict__ eps, float* __restrict__ out)
{
    int i = blockIdx.x*blockDim.x + threadIdx.x;
    if (i >= BB*LDIM) return;
    if (i == 0) out[OFF_XP] = 0.0f;
    int s = i >> 4, k = i & 15;
    float mean = g_ms[s*2*LDIM + k];
    float logs = g_ms[s*2*LDIM + LDIM + k];
    float sd = expf(logs) + 1e-6f;
    out[OFF_MEAN + i] = mean;
    out[OFF_STD  + i] = sd;
    g_z[i] = mean + eps[i]*sd;
}

// ---------------- base_c ----------------
__global__ void bc_kernel(const float* __restrict__ emb, const int* __restrict__ cond,
                          const float* __restrict__ cwc)
{
    __shared__ float cw[CDIM*CDIM];
    int tid = threadIdx.x;
    for (int i = tid; i < CDIM*CDIM; i += 256) cw[i] = cwc[i];
    __syncthreads();
    int idx = blockIdx.x*256 + tid;
    if (idx >= BB*CDIM) return;
    int s = idx >> 5, j = idx & 31;
    const float* er = emb + cond[s]*CDIM;
    float a = 0.0f;
    #pragma unroll
    for (int k = 0; k < CDIM; k++) a += er[k]*cw[j*CDIM + k];
    g_bc[idx] = a;
}

// ---------------- hypernet stage 1 ----------------
__global__ void hyper1_kernel(const float* __restrict__ hw1, const float* __restrict__ hb1,
                              const float* __restrict__ hw2, const float* __restrict__ hb2)
{
    __shared__ float x1[OHID];
    int t = blockIdx.x, j = threadIdx.x;
    float tv = 10.0f - 0.3125f * (float)t;
    x1[j] = tanhf(tv*hw1[j] + hb1[j]);
    __syncthreads();
    float a = hb2[j];
    #pragma unroll 8
    for (int k = 0; k < OHID; k++) a += x1[k]*hw2[j*OHID + k];
    g_x2[t*OHID + j] = tanhf(a);
}

// ---------------- hypernet stage 2 ----------------
#define H2_ROWS 12
__global__ void hyper2_kernel(const float* __restrict__ hw3, const float* __restrict__ hb3)
{
    __shared__ float rows[H2_ROWS*257];
    __shared__ float x2s[NTT*257];
    int tid = threadIdx.x;
    int r0 = blockIdx.x * H2_ROWS;
    for (int i = tid; i < H2_ROWS*256; i += 256) {
        int r = i >> 8, k = i & 255;
        if (r0 + r < P3SZ) rows[r*257 + k] = hw3[(size_t)(r0 + r)*256 + k];
    }
    for (int i = tid; i < NTT*256; i += 256) {
        int t = i >> 8, k = i & 255;
        x2s[t*257 + k] = g_x2[i];
    }
    __syncthreads();
    for (int o = tid; o < H2_ROWS*NTT; o += 256) {
        int r = o / NTT, t = o - r*NTT;
        if (r0 + r >= P3SZ) continue;
        float a = hb3[r0 + r];
        #pragma unroll 8
        for (int k = 0; k < 256; k++) a += rows[r*257 + k]*x2s[t*257 + k];
        g_p[t*P3SZ + r0 + r] = a;
    }
}

// ---------------- hypernet stage 3 ----------------
__global__ void hyper3_kernel()
{
    int t = blockIdx.x;
    int j = threadIdx.x;
    const float* p = g_p + t*P3SZ;
    int sub = j >> 5, rem = j & 31, j4 = rem >> 2, q = rem & 3;
    float wu = 0.0f;
    #pragma unroll
    for (int k = 0; k < LDIM; k++) {
        float Wv = p[j*LDIM + k];
        float Uv = p[4096 + j*LDIM + k] * sigm(p[8192 + j*LDIM + k]);
        wu += Wv*Uv;
        reinterpret_cast<float*>(&g_Wp[((t*16 + k)*8 + j4)*8 + sub])[q] = Wv;
        reinterpret_cast<float*>(&g_Up[((t*16 + k)*8 + j4)*8 + sub])[q] = Uv;
    }
    reinterpret_cast<float*>(&g_Bp [t*64 + j4*8 + sub])[q] = p[12288 + j];
    reinterpret_cast<float*>(&g_wup[t*64 + j4*8 + sub])[q] = wu;
}

// ---------------- launch ----------------
extern "C" void kernel_launch(void* const* d_in, const int* in_sizes, int n_in,
                              void* d_out, int out_size)
{
    const float* input = (const float*)d_in[0];
    const float* eps   = (const float*)d_in[1];
    const float* ew0   = (const float*)d_in[2];
    const float* eb0   = (const float*)d_in[3];
    const float* ew1   = (const float*)d_in[4];
    const float* eb1   = (const float*)d_in[5];
    const float* ew2   = (const float*)d_in[6];
    const float* eb2   = (const float*)d_in[7];
    const float* dw0   = (const float*)d_in[8];
    const float* db0   = (const float*)d_in[9];
    const float* dw1   = (const float*)d_in[10];
    const float* db1   = (const float*)d_in[11];
    const float* dw2   = (const float*)d_in[12];
    const float* db2   = (const float*)d_in[13];
    const float* emb   = (const float*)d_in[14];
    const float* cwz   = (const float*)d_in[15];
    const float* cbz   = (const float*)d_in[16];
    const float* cwc   = (const float*)d_in[17];
    const float* cbc   = (const float*)d_in[18];
    const float* hw1   = (const float*)d_in[19];
    const float* hb1   = (const float*)d_in[20];
    const float* hw2   = (const float*)d_in[21];
    const float* hb2   = (const float*)d_in[22];
    const float* hw3   = (const float*)d_in[23];
    const float* hb3   = (const float*)d_in[24];
    const int*   cond  = (const int*)  d_in[25];
    float* out = (float*)d_out;

    float *bufA, *bufB, *ms, *z;
    cudaGetSymbolAddress((void**)&bufA, g_bufA);
    cudaGetSymbolAddress((void**)&bufB, g_bufB);
    cudaGetSymbolAddress((void**)&ms,   g_ms);
    cudaGetSymbolAddress((void**)&z,    g_z);

    dim3 blk(256);

    // (1-3) CNF precompute prologue (independent of encoder)
    bc_kernel<<<(BB*CDIM)/256, 256>>>(emb, cond, cwc);
    hyper1_kernel<<<NTT, 256>>>(hw1, hb1, hw2, hb2);
    hyper2_kernel<<<(P3SZ + H2_ROWS - 1)/H2_ROWS, 256>>>(hw3, hb3);

    // (4) big GEMM in profiled slot
    gemm_nt<ACT_ELU ><<<dim3(4, 64), blk>>>(input, ew0, eb0, bufA, BB, HID, DIN);

    hyper3_kernel<<<NTT, 256>>>();

    gemm_nt<ACT_TANH><<<dim3(4, 64), blk>>>(bufA,  ew1, eb1, bufB, BB, HID, HID);
    gemm_nt<ACT_NONE><<<dim3(1, 64), blk>>>(bufB,  ew2, eb2, ms,   BB, 2*LDIM, HID);
    zstats_kernel<<<(BB*LDIM)/256, 256>>>(eps, out);   // also zeros out[OFF_XP]

    gemm_nt<ACT_ELU ><<<dim3(4, 64), blk>>>(z,    dw0, db0, bufA, BB, HID, LDIM);
    gemm_nt<ACT_TANH><<<dim3(4, 64), blk>>>(bufA, dw1, db1, bufB, BB, HID, HID);

    // fused: d3 (448 blocks) + CNF (128 blocks), interleaved
    fused_d3_cnf<<<576, blk>>>(bufB, dw2, db2, out, cwz, cbz, cbc, out);
}

// round 17
// speedup vs baseline: 1.1943x; 1.1580x over previous
#include <cuda_runtime.h>
#include <math.h>
#include <stdint.h>

// ---------------- problem constants ----------------
#define BB    8192
#define DIN   784
#define HID   512
#define LDIM  16
#define CDIM  32
#define OHID  256
#define WIDN  256
#define P3SZ  (3*WIDN*LDIM + WIDN)   // 12544
#define NTT   33

#define OFF_XP   (BB*DIN)
#define OFF_MEAN (OFF_XP + 1)
#define OFF_STD  (OFF_MEAN + BB*LDIM)

typedef unsigned long long ull;

// ---------------- f32x2 helpers ----------------
__device__ __forceinline__ ull f2dup(float x) {
    ull r; asm("mov.b64 %0, {%1, %1};" : "=l"(r) : "f"(x)); return r;
}
__device__ __forceinline__ ull f2pack(float x, float y) {
    ull r; asm("mov.b64 %0, {%1, %2};" : "=l"(r) : "f"(x), "f"(y)); return r;
}
__device__ __forceinline__ void f2unpack(ull v, float& x, float& y) {
    asm("mov.b64 {%0, %1}, %2;" : "=f"(x), "=f"(y) : "l"(v));
}
__device__ __forceinline__ void ffma2(ull& d, ull a, ull b) {
    asm("fma.rn.f32x2 %0, %1, %2, %0;" : "+l"(d) : "l"(a), "l"(b));
}

// ---------------- fast transcendentals (CNF only) ----------------
__device__ __forceinline__ float tanha(float x) {
    float r; asm("tanh.approx.f32 %0, %1;" : "=f"(r) : "f"(x)); return r;
}
__device__ __forceinline__ float sigma_fast(float x) {
    float t = -1.4426950408889634f * x;
    float e; asm("ex2.approx.f32 %0, %1;" : "=f"(e) : "f"(t));
    float d = 1.0f + e;
    float r; asm("rcp.approx.f32 %0, %1;" : "=f"(r) : "f"(d));
    return r;
}

__device__ __forceinline__ float sigm(float x) { return 1.0f/(1.0f+expf(-x)); }

// ---------------- device scratch ----------------
__device__ float  g_bufA[BB*HID];
__device__ float  g_bufB[BB*HID];
__device__ float  g_ms[BB*2*LDIM];
__device__ float  g_z[BB*LDIM];
__device__ float  g_bc[BB*CDIM];
__device__ float  g_x2[NTT*OHID];
__device__ float  g_p[NTT*P3SZ];
__device__ float4 g_Wp[NTT*16*64];
__device__ float4 g_Up[NTT*16*64];
__device__ float4 g_Bp[NTT*64];
__device__ float4 g_wup[NTT*64];

// ---------------- generic NT SGEMM (exact R8) ----------------
enum { ACT_NONE=0, ACT_ELU=1, ACT_TANH=2, ACT_SIG=3 };

template<int ACT>
__global__ __launch_bounds__(256) void gemm_nt(
    const float* __restrict__ A, const float* __restrict__ W,
    const float* __restrict__ bias, float* __restrict__ C,
    int M, int N, int K)
{
    __shared__ float As[16][128];
    __shared__ float Bs[16][128];
    const int tid = threadIdx.x;
    const int tx = tid & 15, ty = tid >> 4;
    const int m0 = blockIdx.y * 128, n0 = blockIdx.x * 128;

    ull acc2[4][8];
    #pragma unroll
    for (int i = 0; i < 4; i++)
        #pragma unroll
        for (int j = 0; j < 8; j++) acc2[i][j] = 0ull;

    for (int k0 = 0; k0 < K; k0 += 16) {
        #pragma unroll
        for (int q = 0; q < 2; q++) {
            int l = tid*2 + q;
            int r = l >> 2, c = l & 3;
            float4 v = *reinterpret_cast<const float4*>(A + (size_t)(m0 + r)*K + k0 + c*4);
            As[c*4+0][r] = v.x; As[c*4+1][r] = v.y; As[c*4+2][r] = v.z; As[c*4+3][r] = v.w;
        }
        #pragma unroll
        for (int q = 0; q < 2; q++) {
            int l = tid*2 + q;
            int r = l >> 2, c = l & 3;
            float4 v = make_float4(0.f, 0.f, 0.f, 0.f);
            if (n0 + r < N)
                v = *reinterpret_cast<const float4*>(W + (size_t)(n0 + r)*K + k0 + c*4);
            Bs[c*4+0][r] = v.x; Bs[c*4+1][r] = v.y; Bs[c*4+2][r] = v.z; Bs[c*4+3][r] = v.w;
        }
        __syncthreads();
        #pragma unroll
        for (int k = 0; k < 16; k++) {
            const ulonglong2* arow = reinterpret_cast<const ulonglong2*>(&As[k][0]);
            ulonglong2 alo = arow[ty];
            ulonglong2 ahi = arow[16 + ty];
            ull ap[4] = { alo.x, alo.y, ahi.x, ahi.y };
            float4 b0 = *reinterpret_cast<const float4*>(&Bs[k][tx*4]);
            float4 b1 = *reinterpret_cast<const float4*>(&Bs[k][64 + tx*4]);
            ull bd[8] = { f2dup(b0.x), f2dup(b0.y), f2dup(b0.z), f2dup(b0.w),
                          f2dup(b1.x), f2dup(b1.y), f2dup(b1.z), f2dup(b1.w) };
            #pragma unroll
            for (int i = 0; i < 4; i++)
                #pragma unroll
                for (int j = 0; j < 8; j++)
                    ffma2(acc2[i][j], ap[i], bd[j]);
        }
        __syncthreads();
    }

    int cols[8];
    #pragma unroll
    for (int j = 0; j < 4; j++) { cols[j] = n0 + tx*4 + j; cols[j+4] = n0 + 64 + tx*4 + j; }
    float bcol[8];
    #pragma unroll
    for (int j = 0; j < 8; j++) bcol[j] = (cols[j] < N) ? bias[cols[j]] : 0.0f;

    #pragma unroll
    for (int ip = 0; ip < 4; ip++) {
        int rlo = m0 + ((ip < 2) ? (ty*4 + ip*2) : (64 + ty*4 + (ip-2)*2));
        int rhi = rlo + 1;
        #pragma unroll
        for (int j = 0; j < 8; j++) {
            if (cols[j] < N) {
                float vlo, vhi;
                f2unpack(acc2[ip][j], vlo, vhi);
                vlo += bcol[j]; vhi += bcol[j];
                if (ACT == ACT_ELU)  { vlo = (vlo > 0.0f) ? vlo : expm1f(vlo);
                                       vhi = (vhi > 0.0f) ? vhi : expm1f(vhi); }
                if (ACT == ACT_TANH) { vlo = tanhf(vlo); vhi = tanhf(vhi); }
                if (ACT == ACT_SIG)  { vlo = 1.0f/(1.0f+expf(-vlo));
                                       vhi = 1.0f/(1.0f+expf(-vhi)); }
                C[(size_t)rlo*N + cols[j]] = vlo;
                C[(size_t)rhi*N + cols[j]] = vhi;
            }
        }
    }
}

// ---------------- z stats (+ zero x_probs accumulator) ----------------
__global__ void zstats_kernel(const float* __restrict__ eps, float* __restrict__ out)
{
    int i = blockIdx.x*blockDim.x + threadIdx.x;
    if (i >= BB*LDIM) return;
    if (i == 0) out[OFF_XP] = 0.0f;
    int s = i >> 4, k = i & 15;
    float mean = g_ms[s*2*LDIM + k];
    float logs = g_ms[s*2*LDIM + LDIM + k];
    float sd = expf(logs) + 1e-6f;
    out[OFF_MEAN + i] = mean;
    out[OFF_STD  + i] = sd;
    g_z[i] = mean + eps[i]*sd;
}

// ---------------- base_c ----------------
__global__ void bc_kernel(const float* __restrict__ emb, const int* __restrict__ cond,
                          const float* __restrict__ cwc)
{
    __shared__ float cw[CDIM*CDIM];
    int tid = threadIdx.x;
    for (int i = tid; i < CDIM*CDIM; i += 256) cw[i] = cwc[i];
    __syncthreads();
    int idx = blockIdx.x*256 + tid;
    if (idx >= BB*CDIM) return;
    int s = idx >> 5, j = idx & 31;
    const float* er = emb + cond[s]*CDIM;
    float a = 0.0f;
    #pragma unroll
    for (int k = 0; k < CDIM; k++) a += er[k]*cw[j*CDIM + k];
    g_bc[idx] = a;
}

// ---------------- hypernet stage 1 ----------------
__global__ void hyper1_kernel(const float* __restrict__ hw1, const float* __restrict__ hb1,
                              const float* __restrict__ hw2, const float* __restrict__ hb2)
{
    __shared__ float x1[OHID];
    int t = blockIdx.x, j = threadIdx.x;
    float tv = 10.0f - 0.3125f * (float)t;
    x1[j] = tanhf(tv*hw1[j] + hb1[j]);
    __syncthreads();
    float a = hb2[j];
    #pragma unroll 8
    for (int k = 0; k < OHID; k++) a += x1[k]*hw2[j*OHID + k];
    g_x2[t*OHID + j] = tanhf(a);
}

// ---------------- hypernet stage 2 ----------------
#define H2_ROWS 12
__global__ void hyper2_kernel(const float* __restrict__ hw3, const float* __restrict__ hb3)
{
    __shared__ float rows[H2_ROWS*257];
    __shared__ float x2s[NTT*257];
    int tid = threadIdx.x;
    int r0 = blockIdx.x * H2_ROWS;
    for (int i = tid; i < H2_ROWS*256; i += 256) {
        int r = i >> 8, k = i & 255;
        if (r0 + r < P3SZ) rows[r*257 + k] = hw3[(size_t)(r0 + r)*256 + k];
    }
    for (int i = tid; i < NTT*256; i += 256) {
        int t = i >> 8, k = i & 255;
        x2s[t*257 + k] = g_x2[i];
    }
    __syncthreads();
    for (int o = tid; o < H2_ROWS*NTT; o += 256) {
        int r = o / NTT, t = o - r*NTT;
        if (r0 + r >= P3SZ) continue;
        float a = hb3[r0 + r];
        #pragma unroll 8
        for (int k = 0; k < 256; k++) a += rows[r*257 + k]*x2s[t*257 + k];
        g_p[t*P3SZ + r0 + r] = a;
    }
}

// ---------------- hypernet stage 3 ----------------
__global__ void hyper3_kernel()
{
    int t = blockIdx.x;
    int j = threadIdx.x;
    const float* p = g_p + t*P3SZ;
    int sub = j >> 5, rem = j & 31, j4 = rem >> 2, q = rem & 3;
    float wu = 0.0f;
    #pragma unroll
    for (int k = 0; k < LDIM; k++) {
        float Wv = p[j*LDIM + k];
        float Uv = p[4096 + j*LDIM + k] * sigm(p[8192 + j*LDIM + k]);
        wu += Wv*Uv;
        reinterpret_cast<float*>(&g_Wp[((t*16 + k)*8 + j4)*8 + sub])[q] = Wv;
        reinterpret_cast<float*>(&g_Up[((t*16 + k)*8 + j4)*8 + sub])[q] = Uv;
    }
    reinterpret_cast<float*>(&g_Bp [t*64 + j4*8 + sub])[q] = p[12288 + j];
    reinterpret_cast<float*>(&g_wup[t*64 + j4*8 + sub])[q] = wu;
}

// ---------------- CNF main kernel: R8 + tile-reuse (loads only at st1/st3) ----------------
#define SPT 2   // samples per thread

__global__ __launch_bounds__(256, 1) void cnf_kernel(
    const float* __restrict__ cwz, const float* __restrict__ cbz,
    const float* __restrict__ cbc, float* __restrict__ out)
{
    __shared__ float4 shW[16*64];     // 16 KB
    __shared__ float4 shU[16*64];     // 16 KB
    __shared__ float4 shB[64];
    __shared__ float4 shwu[64];
    __shared__ float  shcwz[16*32];   // k-major: shcwz[k*32+j] = cwz[j*16+k]
    __shared__ float  shcb[32];
    __shared__ float  redbuf[32];

    const int tid  = threadIdx.x;
    const int sub  = tid & 7;
    const int s0   = blockIdx.x*64 + (tid >> 3);   // second sample = s0 + 32
    const unsigned lane = tid & 31;
    const int gbase = lane & ~7;

    for (int i = tid; i < 512; i += 256) {
        int j = i >> 4, k = i & 15;
        shcwz[k*32 + j] = cwz[i];
    }
    if (tid < 32) shcb[tid] = cbz[tid] + cbc[tid];

    // preload tile 0 (used by step 0 / st0)
    {
        const float4* srcW = g_Wp;
        const float4* srcU = g_Up;
        #pragma unroll
        for (int i = 0; i < 4; i++) shW[tid + i*256] = srcW[tid + i*256];
        #pragma unroll
        for (int i = 0; i < 4; i++) shU[tid + i*256] = srcU[tid + i*256];
        if (tid < 64)                   shB[tid]      = g_Bp [tid];
        else if (tid < 128)             shwu[tid-64]  = g_wup[tid - 64];
    }

    float z[SPT][16], zs[SPT][16], accum[SPT][16];
    float bc[SPT][4];
    #pragma unroll
    for (int s = 0; s < SPT; s++) {
        int sg = s0 + s*32;
        #pragma unroll
        for (int k = 0; k < 16; k++) z[s][k] = g_z[sg*16 + k];
        float4 b = *reinterpret_cast<const float4*>(&g_bc[sg*32 + sub*4]);
        bc[s][0] = b.x; bc[s][1] = b.y; bc[s][2] = b.z; bc[s][3] = b.w;
    }
    __syncthreads();
    float cb[4];
    #pragma unroll
    for (int q = 0; q < 4; q++) cb[q] = shcb[sub*4 + q];

    const float h   = -0.625f;
    const float h6  = -0.625f/6.0f;
    const float k2f = 1.0f + 0.5f*h;
    const float k3f = 1.0f + 0.5f*h*k2f;
    const float k4f = 1.0f + h*k3f;
    const float gfac = 1.0f + h6*(1.0f + 2.0f*k2f + 2.0f*k3f + k4f);
    const float inv = 1.0f/256.0f;

    float lp[SPT] = {0.0f, 0.0f};
    float gpow = 1.0f;

    #pragma unroll 1
    for (int step = 0; step < 16; step++) {
        float lacc[SPT] = {0.0f, 0.0f};
        #pragma unroll
        for (int s = 0; s < SPT; s++)
            #pragma unroll
            for (int k = 0; k < 16; k++) { accum[s][k] = 0.0f; zs[s][k] = z[s][k]; }

        #pragma unroll 1
        for (int st = 0; st < 4; st++) {
            int tidx = 2*step + ((st == 0) ? 0 : ((st == 3) ? 2 : 1));
            float sc = gpow * ((st == 0) ? 1.0f : (st == 1) ? k2f : (st == 2) ? k3f : k4f);

            // tile is already resident for st0 (preload / prev st3) and st2 (same as st1)
            if (st == 1 || st == 3) {
                __syncthreads();
                const float4* srcW = g_Wp + tidx*1024;
                const float4* srcU = g_Up + tidx*1024;
                #pragma unroll
                for (int i = 0; i < 4; i++) shW[tid + i*256] = srcW[tid + i*256];
                #pragma unroll
                for (int i = 0; i < 4; i++) shU[tid + i*256] = srcU[tid + i*256];
                if (tid < 64)                   shB[tid]      = g_Bp [tidx*64 + tid];
                else if (tid < 128)             shwu[tid-64]  = g_wup[tidx*64 + tid - 64];
                __syncthreads();
            }

            // a[s][q] for j = sub*4+q
            float a[SPT][4];
            #pragma unroll
            for (int s = 0; s < SPT; s++)
                #pragma unroll
                for (int q = 0; q < 4; q++) a[s][q] = sc*bc[s][q] + cb[q];
            #pragma unroll
            for (int k = 0; k < 16; k++) {
                float4 cw = *reinterpret_cast<const float4*>(&shcwz[k*32 + sub*4]);
                #pragma unroll
                for (int s = 0; s < SPT; s++) {
                    a[s][0] += zs[s][k]*cw.x; a[s][1] += zs[s][k]*cw.y;
                    a[s][2] += zs[s][k]*cw.z; a[s][3] += zs[s][k]*cw.w;
                }
            }

            // part 1: w2[s][p] (packed pairs over j) = zc . W, zc computed lazily per k
            ull w2[SPT][16];
            #pragma unroll
            for (int s = 0; s < SPT; s++)
                #pragma unroll
                for (int p = 0; p < 16; p++) w2[s][p] = 0ull;

            const ulonglong2* shWu = reinterpret_cast<const ulonglong2*>(shW);
            #pragma unroll
            for (int k = 0; k < 16; k++) {
                ull zd[SPT];
                #pragma unroll
                for (int s = 0; s < SPT; s++) {
                    float a1 = __shfl_sync(0xffffffffu, a[s][k & 3], gbase + (k >> 2));
                    float a2 = __shfl_sync(0xffffffffu, a[s][k & 3], gbase + 4 + (k >> 2));
                    zd[s] = f2dup(tanha(a1) * sigma_fast(a2));
                }
                #pragma unroll
                for (int j4 = 0; j4 < 8; j4++) {
                    ulonglong2 wv = shWu[(k*8 + j4)*8 + sub];
                    #pragma unroll
                    for (int s = 0; s < SPT; s++) {
                        ffma2(w2[s][j4*2+0], zd[s], wv.x);
                        ffma2(w2[s][j4*2+1], zd[s], wv.y);
                    }
                }
            }

            // h = tanh(w + B); trace partial; repack h into w2
            float tr[SPT] = {0.0f, 0.0f};
            #pragma unroll
            for (int j4 = 0; j4 < 8; j4++) {
                float4 bv  = shB[j4*8 + sub];
                float4 wuv = shwu[j4*8 + sub];
                #pragma unroll
                for (int s = 0; s < SPT; s++) {
                    float l0, h0, l1, h1;
                    f2unpack(w2[s][j4*2+0], l0, h0);
                    f2unpack(w2[s][j4*2+1], l1, h1);
                    float t0 = tanha(l0 + bv.x); tr[s] += (1.0f - t0*t0)*wuv.x;
                    float t1 = tanha(h0 + bv.y); tr[s] += (1.0f - t1*t1)*wuv.y;
                    float t2 = tanha(l1 + bv.z); tr[s] += (1.0f - t2*t2)*wuv.z;
                    float t3 = tanha(h1 + bv.w); tr[s] += (1.0f - t3*t3)*wuv.w;
                    w2[s][j4*2+0] = f2pack(t0, t1);
                    w2[s][j4*2+1] = f2pack(t2, t3);
                }
            }

            // part 2: dz[k] = h . U[:,k], fused per-k reduce + state update
            float wgt = (st == 0 || st == 3) ? 1.0f : 2.0f;
            float cf  = (st < 2) ? 0.5f*h : h;
            const ulonglong2* shUu = reinterpret_cast<const ulonglong2*>(shU);
            #pragma unroll
            for (int k = 0; k < 16; k++) {
                ull da[SPT], db[SPT];
                #pragma unroll
                for (int s = 0; s < SPT; s++) { da[s] = 0ull; db[s] = 0ull; }
                #pragma unroll
                for (int j4 = 0; j4 < 8; j4++) {
                    ulonglong2 uv = shUu[(k*8 + j4)*8 + sub];
                    #pragma unroll
                    for (int s = 0; s < SPT; s++) {
                        ffma2(da[s], w2[s][j4*2+0], uv.x);
                        ffma2(db[s], w2[s][j4*2+1], uv.y);
                    }
                }
                #pragma unroll
                for (int s = 0; s < SPT; s++) {
                    float lo, hi, lo2, hi2;
                    f2unpack(da[s], lo, hi);
                    f2unpack(db[s], lo2, hi2);
                    float d = (lo + lo2) + (hi + hi2);
                    d += __shfl_xor_sync(0xffffffffu, d, 1);
                    d += __shfl_xor_sync(0xffffffffu, d, 2);
                    d += __shfl_xor_sync(0xffffffffu, d, 4);
                    d *= inv;
                    accum[s][k] += wgt*d;
                    if (st < 3) zs[s][k] = z[s][k] + cf*d;
                }
            }

            #pragma unroll
            for (int s = 0; s < SPT; s++) {
                float t = tr[s];
                t += __shfl_xor_sync(0xffffffffu, t, 1);
                t += __shfl_xor_sync(0xffffffffu, t, 2);
                t += __shfl_xor_sync(0xffffffffu, t, 4);
                lacc[s] += wgt * (-t*inv);
            }
        }

        #pragma unroll
        for (int s = 0; s < SPT; s++) {
            #pragma unroll
            for (int k = 0; k < 16; k++) z[s][k] += h6*accum[s][k];
            lp[s] += h6*lacc[s];
        }
        gpow *= gfac;
    }

    // logp_x = -0.5*(16*log(2pi) + |z|^2) - lp ; accumulate mean over both samples
    float lx = 0.0f;
    #pragma unroll
    for (int s = 0; s < SPT; s++) {
        float sq = 0.0f;
        #pragma unroll
        for (int k = 0; k < 16; k++) sq += z[s][k]*z[s][k];
        lx += -0.5f*(16.0f*1.8378770664093453f + sq) - lp[s];
    }

    __syncthreads();
    if (sub == 0) redbuf[tid >> 3] = lx;
    __syncthreads();
    if (tid < 32) {
        float v = redbuf[tid];
        #pragma unroll
        for (int m = 16; m >= 1; m >>= 1) v += __shfl_xor_sync(0xffffffffu, v, m);
        if (tid == 0) atomicAdd(&out[OFF_XP], v * (1.0f/(float)BB));
    }
}

// ---------------- launch ----------------
extern "C" void kernel_launch(void* const* d_in, const int* in_sizes, int n_in,
                              void* d_out, int out_size)
{
    const float* input = (const float*)d_in[0];
    const float* eps   = (const float*)d_in[1];
    const float* ew0   = (const float*)d_in[2];
    const float* eb0   = (const float*)d_in[3];
    const float* ew1   = (const float*)d_in[4];
    const float* eb1   = (const float*)d_in[5];
    const float* ew2   = (const float*)d_in[6];
    const float* eb2   = (const float*)d_in[7];
    const float* dw0   = (const float*)d_in[8];
    const float* db0   = (const float*)d_in[9];
    const float* dw1   = (const float*)d_in[10];
    const float* db1   = (const float*)d_in[11];
    const float* dw2   = (const float*)d_in[12];
    const float* db2   = (const float*)d_in[13];
    const float* emb   = (const float*)d_in[14];
    const float* cwz   = (const float*)d_in[15];
    const float* cbz   = (const float*)d_in[16];
    const float* cwc   = (const float*)d_in[17];
    const float* cbc   = (const float*)d_in[18];
    const float* hw1   = (const float*)d_in[19];
    const float* hb1   = (const float*)d_in[20];
    const float* hw2   = (const float*)d_in[21];
    const float* hb2   = (const float*)d_in[22];
    const float* hw3   = (const float*)d_in[23];
    const float* hb3   = (const float*)d_in[24];
    const int*   cond  = (const int*)  d_in[25];
    float* out = (float*)d_out;

    float *bufA, *bufB, *ms, *z;
    cudaGetSymbolAddress((void**)&bufA, g_bufA);
    cudaGetSymbolAddress((void**)&bufB, g_bufB);
    cudaGetSymbolAddress((void**)&ms,   g_ms);
    cudaGetSymbolAddress((void**)&z,    g_z);

    dim3 blk(256);

    // CNF precompute prologue (independent of encoder)
    bc_kernel<<<(BB*CDIM)/256, 256>>>(emb, cond, cwc);
    hyper1_kernel<<<NTT, 256>>>(hw1, hb1, hw2, hb2);
    hyper2_kernel<<<(P3SZ + H2_ROWS - 1)/H2_ROWS, 256>>>(hw3, hb3);

    // big GEMM in profiled slot
    gemm_nt<ACT_ELU ><<<dim3(4, 64), blk>>>(input, ew0, eb0, bufA, BB, HID, DIN);

    hyper3_kernel<<<NTT, 256>>>();

    gemm_nt<ACT_TANH><<<dim3(4, 64), blk>>>(bufA,  ew1, eb1, bufB, BB, HID, HID);
    gemm_nt<ACT_NONE><<<dim3(1, 64), blk>>>(bufB,  ew2, eb2, ms,   BB, 2*LDIM, HID);
    zstats_kernel<<<(BB*LDIM)/256, 256>>>(eps, out);   // also zeros out[OFF_XP]

    gemm_nt<ACT_ELU ><<<dim3(4, 64), blk>>>(z,    dw0, db0, bufA, BB, HID, LDIM);
    gemm_nt<ACT_TANH><<<dim3(4, 64), blk>>>(bufA, dw1, db1, bufB, BB, HID, HID);
    gemm_nt<ACT_SIG ><<<dim3(7, 64), blk>>>(bufB, dw2, db2, out,  BB, DIN, HID);

    // CNF main
    cnf_kernel<<<BB/(32*SPT), 256>>>(cwz, cbz, cbc, out);
}